// round 13
// baseline (speedup 1.0000x reference)
#include <cuda_runtime.h>
#include <cuda_fp16.h>
#include <math_constants.h>
#include <cstddef>
#include <cstdint>

#define B_  16
#define T_  750
#define D_  2048
#define C_  20
constexpr int M_TOTAL = B_ * T_;     // 12000
constexpr int K_DIM   = 3 * D_;      // 6144
constexpr int K_EASY  = T_ / 5;      // 150
constexpr int K_HARD  = T_ / 20;     // 37

// ---- output offsets ----
constexpr size_t OFF_VS  = 0;
constexpr size_t OFF_EA  = OFF_VS + (size_t)B_ * C_;
constexpr size_t OFF_EB  = OFF_EA + (size_t)B_ * K_EASY * D_;
constexpr size_t OFF_HA  = OFF_EB + (size_t)B_ * K_EASY * D_;
constexpr size_t OFF_HB  = OFF_HA + (size_t)B_ * K_HARD * D_;
constexpr size_t OFF_ACT = OFF_HB + (size_t)B_ * K_HARD * D_;
constexpr size_t OFF_CAS = OFF_ACT + (size_t)B_ * T_;

// ---- scratch ----
__device__ __half g_xh[(size_t)B_ * 752 * D_];   // padded x hi
__device__ __half g_xl[(size_t)B_ * 752 * D_];   // padded x lo
__device__ __half g_wh[(size_t)D_ * K_DIM];      // (64*w1) hi, [n][ko*2048+io]
__device__ __half g_wl[(size_t)D_ * K_DIM];      // (64*w1) lo
__device__ float  g_w2t[D_ * C_];
__device__ float  g_h[(size_t)M_TOTAL * D_];
__device__ int    g_idx[2 * (B_ * K_EASY) + 2 * (B_ * K_HARD)];
__device__ float  g_means[B_ * C_];

// ============================================================
__global__ void pad_split_x(const float* __restrict__ x) {
    int idx = blockIdx.x * blockDim.x + threadIdx.x;
    const int per_b = 752 * (D_ / 4);
    if (idx >= B_ * per_b) return;
    int b  = idx / per_b;
    int r  = idx - b * per_b;
    int t  = r >> 9;
    int d4 = r & 511;
    float4 v = make_float4(0.f, 0.f, 0.f, 0.f);
    if (t >= 1 && t <= T_) {
        v = ((const float4*)x)[((size_t)(b * T_ + (t - 1)) << 9) + d4];
    }
    __half h[4], l[4];
    float f[4] = {v.x, v.y, v.z, v.w};
    #pragma unroll
    for (int i = 0; i < 4; i++) {
        h[i] = __float2half_rn(f[i]);
        l[i] = __float2half_rn(__fsub_rn(f[i], __half2float(h[i])));
    }
    *(uint2*)(g_xh + (size_t)idx * 4) = *(uint2*)h;
    *(uint2*)(g_xl + (size_t)idx * 4) = *(uint2*)l;
}

__global__ void split_w(const float* __restrict__ w1) {
    size_t i = (size_t)blockIdx.x * blockDim.x + threadIdx.x;
    if (i >= (size_t)D_ * K_DIM) return;
    int n  = (int)(i / K_DIM);
    int kc = (int)(i - (size_t)n * K_DIM);
    int ko = kc >> 11;
    int io = kc & 2047;
    float v = w1[(size_t)n * K_DIM + io * 3 + ko] * 64.0f;
    __half h = __float2half_rn(v);
    __half l = __float2half_rn(__fsub_rn(v, __half2float(h)));
    g_wh[i] = h;
    g_wl[i] = l;
}

__global__ void repack_w2_k(const float* __restrict__ w2) {
    int o = blockIdx.x * blockDim.x + threadIdx.x;
    if (o >= D_ * C_) return;
    int d = o / C_, c = o - d * C_;
    g_w2t[o] = w2[(size_t)c * D_ + d];
}

// ============================================================
// conv1 GEMM: fp16 3-product. CTA 128x64, 256 thr (8 warps 4m x 2n,
// warp 32x32). k=64 stages (96), ring 2, 2 CTAs/SM.
// ldmatrix (non-trans); fold every 2 stages (g=128, same k boundaries).
// ============================================================
constexpr int NSTG = K_DIM / 64;      // 96 stages
constexpr int RSB  = 144;             // row stride bytes (128 data + 16 pad)
constexpr int A_RB = 128 * RSB;       // 18432
constexpr int B_RB = 64 * RSB;        // 9216
constexpr int OFF_AH_S = 0;
constexpr int OFF_AL_S = A_RB;
constexpr int OFF_BH_S = 2 * A_RB;
constexpr int OFF_BL_S = 2 * A_RB + B_RB;
constexpr int STAGE_B = 2 * A_RB + 2 * B_RB;   // 55296
constexpr int RING = 2;
constexpr int DIST = 1;
constexpr int DSMEM = RING * STAGE_B;          // 110592

#define CP16(dst, src) \
    asm volatile("cp.async.cg.shared.global [%0], [%1], 16;" :: "r"(dst), "l"(src))
#define CP_COMMIT() asm volatile("cp.async.commit_group;" ::: "memory")
#define CP_WAIT0()  asm volatile("cp.async.wait_group 0;" ::: "memory")

#define MMA_F16(c, a0, a1, a2, a3, b0, b1) \
    asm volatile("mma.sync.aligned.m16n8k16.row.col.f32.f16.f16.f32 " \
        "{%0,%1,%2,%3}, {%4,%5,%6,%7}, {%8,%9}, {%0,%1,%2,%3};" \
        : "+f"((c)[0]), "+f"((c)[1]), "+f"((c)[2]), "+f"((c)[3]) \
        : "r"(a0), "r"(a1), "r"(a2), "r"(a3), "r"(b0), "r"(b1))

#define LDSM4(r0, r1, r2, r3, addr) \
    asm volatile("ldmatrix.sync.aligned.m8n8.x4.shared.b16 {%0,%1,%2,%3}, [%4];" \
        : "=r"(r0), "=r"(r1), "=r"(r2), "=r"(r3) : "r"(addr))

__device__ __forceinline__ uint32_t smem_u32(const void* p) {
    uint32_t a;
    asm("{ .reg .u64 t; cvta.to.shared.u64 t, %1; cvt.u32.u64 %0, t; }" : "=r"(a) : "l"(p));
    return a;
}

__global__ __launch_bounds__(256, 2) void conv1_f16(const float* __restrict__ b1) {
    extern __shared__ char dsm[];
    const uint32_t smb = smem_u32(dsm);

    const int tid  = threadIdx.x;
    const int lane = tid & 31;
    const int wid  = tid >> 5;       // 0..7
    const int wm   = wid & 3;        // m quarter (32 rows)
    const int wn   = wid >> 2;       // n half (32 cols)
    const int bn   = blockIdx.x;     // 0..31
    const int bm   = blockIdx.y;     // 0..93
    const int tig  = lane & 3;
    const int gid  = lane >> 2;

    // ---- copy mapping (per stage, 12 x CP16 per thread) ----
    // A regions: 128 rows x 128B; thread t covers row t>>1, 64B at (t&1)*64.
    // B regions: 64 rows x 128B; thread t covers row t>>2, 32B at (t&3)*32.
    const int arow  = tid >> 1;
    const int aoffB = (tid & 1) * 64;
    const int brow  = tid >> 2;
    const int boffB = (tid & 3) * 32;
    int mA = bm * 128 + arow;
    int mcA = (mA < M_TOTAL) ? mA : 0;
    int bbA = mcA / T_, ttA = mcA - bbA * T_;
    const __half* srcAh = g_xh + (((size_t)(bbA * 752 + ttA)) << 11) + aoffB / 2;
    const __half* srcAl = g_xl + (((size_t)(bbA * 752 + ttA)) << 11) + aoffB / 2;
    const __half* srcBh = g_wh + (size_t)(bn * 64 + brow) * K_DIM + boffB / 2;
    const __half* srcBl = g_wl + (size_t)(bn * 64 + brow) * K_DIM + boffB / 2;
    const uint32_t dstA = (uint32_t)(arow * RSB + aoffB);
    const uint32_t dstB = (uint32_t)(brow * RSB + boffB);

    // ldmatrix lane-address components (non-trans for both A and B)
    const int aLRow = lane & 15;                         // A: row within 16
    const int aLK   = (lane >> 4) << 4;                  // A: k-chunk byte (0/16)
    const int bLRow = (lane & 7) + ((lane >> 4) << 3);   // B: n-row within 16
    const int bLK   = ((lane >> 3) & 1) << 4;            // B: k-chunk byte (0/16)

    float acc[2][4][4], cfr[2][4][4];
    #pragma unroll
    for (int i = 0; i < 2; i++)
        #pragma unroll
        for (int j = 0; j < 4; j++)
            #pragma unroll
            for (int q = 0; q < 4; q++) { acc[i][j][q] = 0.f; cfr[i][j][q] = 0.f; }

    // prologue: stage 0 -> buf 0 (4 A-chunks x2 regions, 2 B-chunks x2 regions)
    {
        uint32_t bp = smb;
        #pragma unroll
        for (int c = 0; c < 4; c++) {
            CP16(bp + OFF_AH_S + dstA + c * 16, srcAh + c * 8);
            CP16(bp + OFF_AL_S + dstA + c * 16, srcAl + c * 8);
        }
        #pragma unroll
        for (int c = 0; c < 2; c++) {
            CP16(bp + OFF_BH_S + dstB + c * 16, srcBh + c * 8);
            CP16(bp + OFF_BL_S + dstB + c * 16, srcBl + c * 8);
        }
        CP_COMMIT();
    }

    #pragma unroll 1
    for (int s = 0; s < NSTG; s++) {
        const int q = s & 1;
        CP_WAIT0();               // group s complete
        __syncthreads();          // all warps done reading buf q (stage s-2... ring2: s-1's buf is q^1)
        if (s + 1 < NSTG) {
            uint32_t bq = smb + (q ^ 1) * STAGE_B;
            const size_t ko = (size_t)(s + 1) * 64;   // halves
            #pragma unroll
            for (int c = 0; c < 4; c++) {
                CP16(bq + OFF_AH_S + dstA + c * 16, srcAh + ko + c * 8);
                CP16(bq + OFF_AL_S + dstA + c * 16, srcAl + ko + c * 8);
            }
            #pragma unroll
            for (int c = 0; c < 2; c++) {
                CP16(bq + OFF_BH_S + dstB + c * 16, srcBh + ko + c * 8);
                CP16(bq + OFF_BL_S + dstB + c * 16, srcBl + ko + c * 8);
            }
        }
        CP_COMMIT();              // one group per iter (empty in tail)

        const uint32_t stU = smb + q * STAGE_B;
        #pragma unroll
        for (int u = 0; u < 4; u++) {    // four k16 steps
            // B fragments via ldmatrix.x4 (non-trans; 2 nt per instruction)
            uint32_t bh[4][2], bl[4][2];
            #pragma unroll
            for (int p = 0; p < 2; p++) {
                int n0 = wn * 32 + p * 16;
                uint32_t ad  = stU + OFF_BH_S + (uint32_t)((n0 + bLRow) * RSB + u * 32 + bLK);
                LDSM4(bh[2*p][0], bh[2*p][1], bh[2*p+1][0], bh[2*p+1][1], ad);
                uint32_t adl = stU + OFF_BL_S + (uint32_t)((n0 + bLRow) * RSB + u * 32 + bLK);
                LDSM4(bl[2*p][0], bl[2*p][1], bl[2*p+1][0], bl[2*p+1][1], adl);
            }
            // A fragments via ldmatrix.x4
            uint32_t ah[2][4], al[2][4];
            #pragma unroll
            for (int mt = 0; mt < 2; mt++) {
                int rb = wm * 32 + mt * 16;
                uint32_t ad  = stU + OFF_AH_S + (uint32_t)((rb + aLRow) * RSB + u * 32 + aLK);
                LDSM4(ah[mt][0], ah[mt][1], ah[mt][2], ah[mt][3], ad);
                uint32_t adl = stU + OFF_AL_S + (uint32_t)((rb + aLRow) * RSB + u * 32 + aLK);
                LDSM4(al[mt][0], al[mt][1], al[mt][2], al[mt][3], adl);
            }
            #pragma unroll
            for (int mt = 0; mt < 2; mt++)
                #pragma unroll
                for (int nt = 0; nt < 4; nt++) {
                    MMA_F16(cfr[mt][nt], ah[mt][0], ah[mt][1], ah[mt][2], ah[mt][3],
                            bh[nt][0], bh[nt][1]);
                    MMA_F16(cfr[mt][nt], al[mt][0], al[mt][1], al[mt][2], al[mt][3],
                            bh[nt][0], bh[nt][1]);
                    MMA_F16(cfr[mt][nt], ah[mt][0], ah[mt][1], ah[mt][2], ah[mt][3],
                            bl[nt][0], bl[nt][1]);
                }
        }

        // fold every 2 stages (g = 128 k terms, same boundaries as before)
        if (s & 1) {
            #pragma unroll
            for (int mt = 0; mt < 2; mt++)
                #pragma unroll
                for (int nt = 0; nt < 4; nt++)
                    #pragma unroll
                    for (int qq = 0; qq < 4; qq++) {
                        float a = acc[mt][nt][qq], c = cfr[mt][nt][qq];
                        float sP = __fadd_rn(a, c);
                        float bb2 = __fsub_rn(sP, a);
                        float err = __fadd_rn(__fsub_rn(a, __fsub_rn(sP, bb2)),
                                              __fsub_rn(c, bb2));
                        acc[mt][nt][qq] = sP;
                        cfr[mt][nt][qq] = err;
                    }
        }
    }

    // epilogue: unscale 2^-6, + bias, relu -> g_h
    #pragma unroll
    for (int mt = 0; mt < 2; mt++) {
        #pragma unroll
        for (int r2 = 0; r2 < 2; r2++) {
            int m = bm * 128 + wm * 32 + mt * 16 + gid + r2 * 8;
            if (m < M_TOTAL) {
                #pragma unroll
                for (int nt = 0; nt < 4; nt++) {
                    int n = bn * 64 + wn * 32 + nt * 8 + tig * 2;
                    float s0 = __fadd_rn(acc[mt][nt][r2*2+0], cfr[mt][nt][r2*2+0]) * 0.015625f;
                    float s1 = __fadd_rn(acc[mt][nt][r2*2+1], cfr[mt][nt][r2*2+1]) * 0.015625f;
                    float v0 = fmaxf(__fadd_rn(s0, b1[n]), 0.f);
                    float v1 = fmaxf(__fadd_rn(s1, b1[n+1]), 0.f);
                    *(float2*)(g_h + (size_t)m * D_ + n) = make_float2(v0, v1);
                }
            }
        }
    }
}

// ============================================================
// cas + actionness (unchanged)
// ============================================================
__global__ __launch_bounds__(256) void cas_kernel(float* __restrict__ cas,
                                                  float* __restrict__ act) {
    int warp = blockIdx.x * 8 + (threadIdx.x >> 5);
    int lane = threadIdx.x & 31;
    int m0 = warp * 4;
    if (m0 >= M_TOTAL) return;

    float acc[4][20];
    #pragma unroll
    for (int r = 0; r < 4; r++)
        #pragma unroll
        for (int c = 0; c < C_; c++) acc[r][c] = 0.f;

    for (int d = lane; d < D_; d += 32) {
        float w[20];
        const float4* wp = (const float4*)(g_w2t + d * C_);
        #pragma unroll
        for (int q = 0; q < 5; q++) {
            float4 t4 = wp[q];
            w[q * 4 + 0] = t4.x; w[q * 4 + 1] = t4.y;
            w[q * 4 + 2] = t4.z; w[q * 4 + 3] = t4.w;
        }
        #pragma unroll
        for (int r = 0; r < 4; r++) {
            float hv = g_h[(size_t)(m0 + r) * D_ + d];
            #pragma unroll
            for (int c = 0; c < C_; c++) acc[r][c] = fmaf(hv, w[c], acc[r][c]);
        }
    }
    #pragma unroll
    for (int r = 0; r < 4; r++) {
        float s = 0.f;
        #pragma unroll
        for (int c = 0; c < C_; c++) {
            double v = (double)acc[r][c];
            #pragma unroll
            for (int off = 16; off; off >>= 1)
                v += __shfl_down_sync(0xffffffffu, v, off);
            if (lane == 0) {
                float cf = fmaxf((float)v, 0.f);
                cas[(size_t)(m0 + r) * C_ + c] = cf;
                s = __fadd_rn(s, cf);
            }
        }
        if (lane == 0) act[m0 + r] = s;
    }
}

// ============================================================
__device__ __forceinline__ void bitonic_sort_desc(float* val, int* idx, int tid) {
    for (int k = 2; k <= 1024; k <<= 1) {
        for (int j = k >> 1; j > 0; j >>= 1) {
            int p = tid ^ j;
            if (p > tid) {
                float v1 = val[tid], v2 = val[p];
                int i1 = idx[tid], i2 = idx[p];
                bool dirFwd = ((tid & k) == 0);
                bool p_before = (v2 > v1) || (v2 == v1 && i2 < i1);
                if (p_before == dirFwd) {
                    val[tid] = v2; val[p] = v1;
                    idx[tid] = i2; idx[p] = i1;
                }
            }
            __syncthreads();
        }
    }
}

__global__ __launch_bounds__(1024) void batch_topk(const float* __restrict__ act) {
    __shared__ float s_act[T_];
    __shared__ float s_bin[T_];
    __shared__ float s_val[1024];
    __shared__ int   s_idx[1024];
    __shared__ float s_med, s_max;

    const int b = blockIdx.x, tid = threadIdx.x;
    const float NEG = -CUDART_INF_F;

    if (tid < T_) s_act[tid] = act[b * T_ + tid];
    __syncthreads();

    s_val[tid] = (tid < T_) ? s_act[tid] : NEG;
    __syncthreads();
    for (int off = 512; off; off >>= 1) {
        if (tid < off) s_val[tid] = fmaxf(s_val[tid], s_val[tid + off]);
        __syncthreads();
    }
    if (tid == 0) s_max = s_val[0];
    __syncthreads();

    s_val[tid] = (tid < T_) ? s_act[tid] : NEG;
    s_idx[tid] = (tid < T_) ? tid : (1 << 20);
    __syncthreads();
    bitonic_sort_desc(s_val, s_idx, tid);
    if (tid < K_EASY) g_idx[b * K_EASY + tid] = s_idx[tid];
    if (tid == 0) s_med = 0.5f * (s_val[374] + s_val[375]);
    __syncthreads();

    s_val[tid] = (tid < T_) ? __fsub_rn(s_max, s_act[tid]) : NEG;
    s_idx[tid] = (tid < T_) ? tid : (1 << 20);
    __syncthreads();
    bitonic_sort_desc(s_val, s_idx, tid);
    if (tid < K_EASY) g_idx[B_ * K_EASY + b * K_EASY + tid] = s_idx[tid];
    __syncthreads();

    if (tid < T_) s_bin[tid] = (s_act[tid] > s_med) ? 1.0f : 0.0f;
    __syncthreads();

    float sc = NEG;
    if (tid < T_) {
        float e3 = 1.f, e6 = 1.f;
        #pragma unroll
        for (int u = -1; u <= 1; u++) {
            int q = tid + u;
            e3 = fminf(e3, (q >= 0 && q < T_) ? s_bin[q] : 0.f);
        }
        #pragma unroll
        for (int u = -3; u <= 2; u++) {
            int q = tid + u;
            e6 = fminf(e6, (q >= 0 && q < T_) ? s_bin[q] : 0.f);
        }
        sc = s_act[tid] * (e3 - e6);
    }
    s_val[tid] = (tid < T_) ? sc : NEG;
    s_idx[tid] = (tid < T_) ? tid : (1 << 20);
    __syncthreads();
    bitonic_sort_desc(s_val, s_idx, tid);
    if (tid < K_HARD) g_idx[2 * B_ * K_EASY + b * K_HARD + tid] = s_idx[tid];
    __syncthreads();

    sc = NEG;
    if (tid < T_) {
        float d3 = 0.f, d6 = 0.f;
        #pragma unroll
        for (int u = -1; u <= 1; u++) {
            int q = tid + u;
            d3 = fmaxf(d3, (q >= 0 && q < T_) ? s_bin[q] : 0.f);
        }
        #pragma unroll
        for (int u = -2; u <= 3; u++) {
            int q = tid + u;
            d6 = fmaxf(d6, (q >= 0 && q < T_) ? s_bin[q] : 0.f);
        }
        sc = s_act[tid] * (d6 - d3);
    }
    s_val[tid] = (tid < T_) ? sc : NEG;
    s_idx[tid] = (tid < T_) ? tid : (1 << 20);
    __syncthreads();
    bitonic_sort_desc(s_val, s_idx, tid);
    if (tid < K_HARD)
        g_idx[2 * B_ * K_EASY + B_ * K_HARD + b * K_HARD + tid] = s_idx[tid];
}

__global__ __launch_bounds__(1024) void video_topk(const float* __restrict__ cas) {
    __shared__ float s_val[1024];
    __shared__ int   s_idx[1024];
    __shared__ float red[32];
    int bc = blockIdx.x;
    int b = bc / C_, c = bc - b * C_;
    int tid = threadIdx.x;
    s_val[tid] = (tid < T_) ? cas[(size_t)(b * T_ + tid) * C_ + c] : -CUDART_INF_F;
    s_idx[tid] = tid;
    __syncthreads();
    bitonic_sort_desc(s_val, s_idx, tid);
    float v = (tid < K_EASY) ? s_val[tid] : 0.f;
    #pragma unroll
    for (int off = 16; off; off >>= 1) v += __shfl_down_sync(0xffffffffu, v, off);
    if ((tid & 31) == 0) red[tid >> 5] = v;
    __syncthreads();
    if (tid < 32) {
        float t = red[tid];
        #pragma unroll
        for (int off = 16; off; off >>= 1) t += __shfl_down_sync(0xffffffffu, t, off);
        if (tid == 0) g_means[b * C_ + c] = t / (float)K_EASY;
    }
}

__global__ void softmax_k(float* __restrict__ out) {
    int b = blockIdx.x;
    int lane = threadIdx.x;
    float v = (lane < C_) ? g_means[b * C_ + lane] : -CUDART_INF_F;
    float mx = v;
    #pragma unroll
    for (int off = 16; off; off >>= 1) mx = fmaxf(mx, __shfl_xor_sync(0xffffffffu, mx, off));
    float e = (lane < C_) ? expf(v - mx) : 0.f;
    float s = e;
    #pragma unroll
    for (int off = 16; off; off >>= 1) s += __shfl_xor_sync(0xffffffffu, s, off);
    if (lane < C_) out[b * C_ + lane] = e / s;
}

__global__ __launch_bounds__(256) void gather_k(float* __restrict__ out) {
    int r = blockIdx.x;
    int b, t;
    size_t dst;
    if (r < B_ * K_EASY) {
        b = r / K_EASY; t = g_idx[r];
        dst = OFF_EA + (size_t)r * D_;
    } else if (r < 2 * B_ * K_EASY) {
        int rr = r - B_ * K_EASY;
        b = rr / K_EASY; t = g_idx[r];
        dst = OFF_EB + (size_t)rr * D_;
    } else if (r < 2 * B_ * K_EASY + B_ * K_HARD) {
        int rr = r - 2 * B_ * K_EASY;
        b = rr / K_HARD; t = g_idx[r];
        dst = OFF_HA + (size_t)rr * D_;
    } else {
        int rr = r - 2 * B_ * K_EASY - B_ * K_HARD;
        b = rr / K_HARD; t = g_idx[r];
        dst = OFF_HB + (size_t)rr * D_;
    }
    const float4* src = (const float4*)(g_h + ((size_t)(b * T_ + t) << 11));
    float4* d = (float4*)(out + dst);
    for (int i = threadIdx.x; i < D_ / 4; i += blockDim.x) d[i] = src[i];
}

// ============================================================
extern "C" void kernel_launch(void* const* d_in, const int* in_sizes, int n_in,
                              void* d_out, int out_size) {
    const float* x  = (const float*)d_in[0];
    const float* w1 = (const float*)d_in[1];
    const float* b1 = (const float*)d_in[2];
    const float* w2 = (const float*)d_in[3];
    float* out = (float*)d_out;

    cudaFuncSetAttribute(conv1_f16, cudaFuncAttributeMaxDynamicSharedMemorySize, DSMEM);

    pad_split_x<<<(B_ * 752 * (D_ / 4) + 255) / 256, 256>>>(x);
    {
        size_t tot = (size_t)D_ * K_DIM;
        split_w<<<(unsigned)((tot + 255) / 256), 256>>>(w1);
    }
    repack_w2_k<<<(D_ * C_ + 255) / 256, 256>>>(w2);
    {
        dim3 g(D_ / 64, (M_TOTAL + 127) / 128);   // (32, 94)
        conv1_f16<<<g, 256, DSMEM>>>(b1);
    }
    cas_kernel<<<(M_TOTAL / 4 + 7) / 8, 256>>>(out + OFF_CAS, out + OFF_ACT);
    batch_topk<<<B_, 1024>>>(out + OFF_ACT);
    video_topk<<<B_ * C_, 1024>>>(out + OFF_CAS);
    softmax_k<<<B_, 32>>>(out + OFF_VS);
    gather_k<<<2 * B_ * K_EASY + 2 * B_ * K_HARD, 256>>>(out);
}

// round 14
// speedup vs baseline: 1.0480x; 1.0480x over previous
#include <cuda_runtime.h>
#include <cuda_fp16.h>
#include <math_constants.h>
#include <cstddef>
#include <cstdint>

#define B_  16
#define T_  750
#define D_  2048
#define C_  20
constexpr int M_TOTAL = B_ * T_;     // 12000
constexpr int K_DIM   = 3 * D_;      // 6144
constexpr int K_EASY  = T_ / 5;      // 150
constexpr int K_HARD  = T_ / 20;     // 37

// ---- output offsets ----
constexpr size_t OFF_VS  = 0;
constexpr size_t OFF_EA  = OFF_VS + (size_t)B_ * C_;
constexpr size_t OFF_EB  = OFF_EA + (size_t)B_ * K_EASY * D_;
constexpr size_t OFF_HA  = OFF_EB + (size_t)B_ * K_EASY * D_;
constexpr size_t OFF_HB  = OFF_HA + (size_t)B_ * K_HARD * D_;
constexpr size_t OFF_ACT = OFF_HB + (size_t)B_ * K_HARD * D_;
constexpr size_t OFF_CAS = OFF_ACT + (size_t)B_ * T_;

// ---- scratch ----
__device__ __half g_xh[(size_t)B_ * 752 * D_];   // padded x hi
__device__ __half g_xl[(size_t)B_ * 752 * D_];   // padded x lo
__device__ __half g_wh[(size_t)D_ * K_DIM];      // (64*w1) hi, [n][ko*2048+io]
__device__ __half g_wl[(size_t)D_ * K_DIM];      // (64*w1) lo
__device__ float  g_w2t[D_ * C_];
__device__ float  g_h[(size_t)M_TOTAL * D_];
__device__ int    g_idx[2 * (B_ * K_EASY) + 2 * (B_ * K_HARD)];
__device__ float  g_means[B_ * C_];

// ============================================================
__global__ void pad_split_x(const float* __restrict__ x) {
    int idx = blockIdx.x * blockDim.x + threadIdx.x;
    const int per_b = 752 * (D_ / 4);
    if (idx >= B_ * per_b) return;
    int b  = idx / per_b;
    int r  = idx - b * per_b;
    int t  = r >> 9;
    int d4 = r & 511;
    float4 v = make_float4(0.f, 0.f, 0.f, 0.f);
    if (t >= 1 && t <= T_) {
        v = ((const float4*)x)[((size_t)(b * T_ + (t - 1)) << 9) + d4];
    }
    __half h[4], l[4];
    float f[4] = {v.x, v.y, v.z, v.w};
    #pragma unroll
    for (int i = 0; i < 4; i++) {
        h[i] = __float2half_rn(f[i]);
        l[i] = __float2half_rn(__fsub_rn(f[i], __half2float(h[i])));
    }
    *(uint2*)(g_xh + (size_t)idx * 4) = *(uint2*)h;
    *(uint2*)(g_xl + (size_t)idx * 4) = *(uint2*)l;
}

__global__ void split_w(const float* __restrict__ w1) {
    size_t i = (size_t)blockIdx.x * blockDim.x + threadIdx.x;
    if (i >= (size_t)D_ * K_DIM) return;
    int n  = (int)(i / K_DIM);
    int kc = (int)(i - (size_t)n * K_DIM);
    int ko = kc >> 11;
    int io = kc & 2047;
    float v = w1[(size_t)n * K_DIM + io * 3 + ko] * 64.0f;
    __half h = __float2half_rn(v);
    __half l = __float2half_rn(__fsub_rn(v, __half2float(h)));
    g_wh[i] = h;
    g_wl[i] = l;
}

__global__ void repack_w2_k(const float* __restrict__ w2) {
    int o = blockIdx.x * blockDim.x + threadIdx.x;
    if (o >= D_ * C_) return;
    int d = o / C_, c = o - d * C_;
    g_w2t[o] = w2[(size_t)c * D_ + d];
}

// ============================================================
// conv1 GEMM: fp16 3-product. CTA 128x64, 256 thr (8 warps 4m x 2n,
// warp 32x32). k=32 stages (192), ring 3, 2 CTAs/SM.
// ldmatrix (non-trans, volatile); MMA non-volatile so ptxas can
// software-pipeline LDSM of u+1 under MMAs of u. Fold every 4 stages.
// ============================================================
constexpr int NSTG = K_DIM / 32;      // 192 stages
constexpr int RSB  = 80;              // row stride bytes (64 data + 16 pad)
constexpr int A_RB = 128 * RSB;       // 10240
constexpr int B_RB = 64 * RSB;        // 5120
constexpr int OFF_AH_S = 0;
constexpr int OFF_AL_S = A_RB;
constexpr int OFF_BH_S = 2 * A_RB;
constexpr int OFF_BL_S = 2 * A_RB + B_RB;
constexpr int STAGE_B = 2 * A_RB + 2 * B_RB;   // 30720
constexpr int RING = 3;
constexpr int DIST = 2;
constexpr int DSMEM = RING * STAGE_B;          // 92160

#define CP16(dst, src) \
    asm volatile("cp.async.cg.shared.global [%0], [%1], 16;" :: "r"(dst), "l"(src))
#define CP_COMMIT() asm volatile("cp.async.commit_group;" ::: "memory")
#define CP_WAIT1()  asm volatile("cp.async.wait_group 1;" ::: "memory")

// NON-volatile: no memory side effects; lets ptxas interleave across u-steps.
#define MMA_F16(c, a0, a1, a2, a3, b0, b1) \
    asm("mma.sync.aligned.m16n8k16.row.col.f32.f16.f16.f32 " \
        "{%0,%1,%2,%3}, {%4,%5,%6,%7}, {%8,%9}, {%0,%1,%2,%3};" \
        : "+f"((c)[0]), "+f"((c)[1]), "+f"((c)[2]), "+f"((c)[3]) \
        : "r"(a0), "r"(a1), "r"(a2), "r"(a3), "r"(b0), "r"(b1))

#define LDSM4(r0, r1, r2, r3, addr) \
    asm volatile("ldmatrix.sync.aligned.m8n8.x4.shared.b16 {%0,%1,%2,%3}, [%4];" \
        : "=r"(r0), "=r"(r1), "=r"(r2), "=r"(r3) : "r"(addr))

__device__ __forceinline__ uint32_t smem_u32(const void* p) {
    uint32_t a;
    asm("{ .reg .u64 t; cvta.to.shared.u64 t, %1; cvt.u32.u64 %0, t; }" : "=r"(a) : "l"(p));
    return a;
}

__global__ __launch_bounds__(256, 2) void conv1_f16(const float* __restrict__ b1) {
    extern __shared__ char dsm[];
    const uint32_t smb = smem_u32(dsm);

    const int tid  = threadIdx.x;
    const int lane = tid & 31;
    const int wid  = tid >> 5;       // 0..7
    const int wm   = wid & 3;        // m quarter (32 rows)
    const int wn   = wid >> 2;       // n half (32 cols)
    const int bn   = blockIdx.x;     // 0..31
    const int bm   = blockIdx.y;     // 0..93
    const int tig  = lane & 3;
    const int gid  = lane >> 2;

    // ---- copy mapping (per stage, 6 x CP16 per thread) ----
    const int arow = tid >> 1;
    const int aoffB = (tid & 1) * 32;
    const int brow = tid >> 2;
    const int boffB = (tid & 3) * 16;
    int mA = bm * 128 + arow;
    int mcA = (mA < M_TOTAL) ? mA : 0;
    int bbA = mcA / T_, ttA = mcA - bbA * T_;
    const __half* srcAh = g_xh + (((size_t)(bbA * 752 + ttA)) << 11) + aoffB / 2;
    const __half* srcAl = g_xl + (((size_t)(bbA * 752 + ttA)) << 11) + aoffB / 2;
    const __half* srcBh = g_wh + (size_t)(bn * 64 + brow) * K_DIM + boffB / 2;
    const __half* srcBl = g_wl + (size_t)(bn * 64 + brow) * K_DIM + boffB / 2;
    const uint32_t dstA = (uint32_t)(arow * RSB + aoffB);
    const uint32_t dstB = (uint32_t)(brow * RSB + boffB);

    // ldmatrix lane-address components (non-trans for both A and B)
    const int aLRow = lane & 15;                         // A: row within 16
    const int aLK   = (lane >> 4) << 4;                  // A: k-chunk byte (0/16)
    const int bLRow = (lane & 7) + ((lane >> 4) << 3);   // B: n-row within 16
    const int bLK   = ((lane >> 3) & 1) << 4;            // B: k-chunk byte (0/16)

    float acc[2][4][4], cfr[2][4][4];
    #pragma unroll
    for (int i = 0; i < 2; i++)
        #pragma unroll
        for (int j = 0; j < 4; j++)
            #pragma unroll
            for (int q = 0; q < 4; q++) { acc[i][j][q] = 0.f; cfr[i][j][q] = 0.f; }

    // prologue
    #pragma unroll
    for (int p = 0; p < DIST; p++) {
        uint32_t bp = smb + p * STAGE_B;
        CP16(bp + OFF_AH_S + dstA,      srcAh + p * 32);
        CP16(bp + OFF_AH_S + dstA + 16, srcAh + p * 32 + 8);
        CP16(bp + OFF_AL_S + dstA,      srcAl + p * 32);
        CP16(bp + OFF_AL_S + dstA + 16, srcAl + p * 32 + 8);
        CP16(bp + OFF_BH_S + dstB,      srcBh + p * 32);
        CP16(bp + OFF_BL_S + dstB,      srcBl + p * 32);
        CP_COMMIT();
    }

    #pragma unroll 1
    for (int s = 0; s < NSTG; s++) {
        const int q = s % RING;
        CP_WAIT1();
        __syncthreads();
        if (s + DIST < NSTG) {
            uint32_t bq = smb + ((s + DIST) % RING) * STAGE_B;
            const size_t ko = (size_t)(s + DIST) * 32;
            CP16(bq + OFF_AH_S + dstA,      srcAh + ko);
            CP16(bq + OFF_AH_S + dstA + 16, srcAh + ko + 8);
            CP16(bq + OFF_AL_S + dstA,      srcAl + ko);
            CP16(bq + OFF_AL_S + dstA + 16, srcAl + ko + 8);
            CP16(bq + OFF_BH_S + dstB,      srcBh + ko);
            CP16(bq + OFF_BL_S + dstB,      srcBl + ko);
        }
        CP_COMMIT();

        const uint32_t stU = smb + q * STAGE_B;
        #pragma unroll
        for (int u = 0; u < 2; u++) {
            // B fragments via ldmatrix.x4 (non-trans; 2 nt per instruction)
            uint32_t bh[4][2], bl[4][2];
            #pragma unroll
            for (int p = 0; p < 2; p++) {
                int n0 = wn * 32 + p * 16;
                uint32_t ad  = stU + OFF_BH_S + (uint32_t)((n0 + bLRow) * RSB + u * 32 + bLK);
                LDSM4(bh[2*p][0], bh[2*p][1], bh[2*p+1][0], bh[2*p+1][1], ad);
                uint32_t adl = stU + OFF_BL_S + (uint32_t)((n0 + bLRow) * RSB + u * 32 + bLK);
                LDSM4(bl[2*p][0], bl[2*p][1], bl[2*p+1][0], bl[2*p+1][1], adl);
            }
            // A fragments via ldmatrix.x4
            uint32_t ah[2][4], al[2][4];
            #pragma unroll
            for (int mt = 0; mt < 2; mt++) {
                int rb = wm * 32 + mt * 16;
                uint32_t ad  = stU + OFF_AH_S + (uint32_t)((rb + aLRow) * RSB + u * 32 + aLK);
                LDSM4(ah[mt][0], ah[mt][1], ah[mt][2], ah[mt][3], ad);
                uint32_t adl = stU + OFF_AL_S + (uint32_t)((rb + aLRow) * RSB + u * 32 + aLK);
                LDSM4(al[mt][0], al[mt][1], al[mt][2], al[mt][3], adl);
            }
            #pragma unroll
            for (int mt = 0; mt < 2; mt++)
                #pragma unroll
                for (int nt = 0; nt < 4; nt++) {
                    MMA_F16(cfr[mt][nt], ah[mt][0], ah[mt][1], ah[mt][2], ah[mt][3],
                            bh[nt][0], bh[nt][1]);
                    MMA_F16(cfr[mt][nt], al[mt][0], al[mt][1], al[mt][2], al[mt][3],
                            bh[nt][0], bh[nt][1]);
                    MMA_F16(cfr[mt][nt], ah[mt][0], ah[mt][1], ah[mt][2], ah[mt][3],
                            bl[nt][0], bl[nt][1]);
                }
        }

        // fold every 4 stages (g = 128 k terms): 2Sum; comp rides in cfr
        if ((s & 3) == 3) {
            #pragma unroll
            for (int mt = 0; mt < 2; mt++)
                #pragma unroll
                for (int nt = 0; nt < 4; nt++)
                    #pragma unroll
                    for (int qq = 0; qq < 4; qq++) {
                        float a = acc[mt][nt][qq], c = cfr[mt][nt][qq];
                        float sP = __fadd_rn(a, c);
                        float bb2 = __fsub_rn(sP, a);
                        float err = __fadd_rn(__fsub_rn(a, __fsub_rn(sP, bb2)),
                                              __fsub_rn(c, bb2));
                        acc[mt][nt][qq] = sP;
                        cfr[mt][nt][qq] = err;
                    }
        }
    }

    // epilogue: unscale 2^-6, + bias, relu -> g_h
    #pragma unroll
    for (int mt = 0; mt < 2; mt++) {
        #pragma unroll
        for (int r2 = 0; r2 < 2; r2++) {
            int m = bm * 128 + wm * 32 + mt * 16 + gid + r2 * 8;
            if (m < M_TOTAL) {
                #pragma unroll
                for (int nt = 0; nt < 4; nt++) {
                    int n = bn * 64 + wn * 32 + nt * 8 + tig * 2;
                    float s0 = __fadd_rn(acc[mt][nt][r2*2+0], cfr[mt][nt][r2*2+0]) * 0.015625f;
                    float s1 = __fadd_rn(acc[mt][nt][r2*2+1], cfr[mt][nt][r2*2+1]) * 0.015625f;
                    float v0 = fmaxf(__fadd_rn(s0, b1[n]), 0.f);
                    float v1 = fmaxf(__fadd_rn(s1, b1[n+1]), 0.f);
                    *(float2*)(g_h + (size_t)m * D_ + n) = make_float2(v0, v1);
                }
            }
        }
    }
}

// ============================================================
// cas + actionness (unchanged)
// ============================================================
__global__ __launch_bounds__(256) void cas_kernel(float* __restrict__ cas,
                                                  float* __restrict__ act) {
    int warp = blockIdx.x * 8 + (threadIdx.x >> 5);
    int lane = threadIdx.x & 31;
    int m0 = warp * 4;
    if (m0 >= M_TOTAL) return;

    float acc[4][20];
    #pragma unroll
    for (int r = 0; r < 4; r++)
        #pragma unroll
        for (int c = 0; c < C_; c++) acc[r][c] = 0.f;

    for (int d = lane; d < D_; d += 32) {
        float w[20];
        const float4* wp = (const float4*)(g_w2t + d * C_);
        #pragma unroll
        for (int q = 0; q < 5; q++) {
            float4 t4 = wp[q];
            w[q * 4 + 0] = t4.x; w[q * 4 + 1] = t4.y;
            w[q * 4 + 2] = t4.z; w[q * 4 + 3] = t4.w;
        }
        #pragma unroll
        for (int r = 0; r < 4; r++) {
            float hv = g_h[(size_t)(m0 + r) * D_ + d];
            #pragma unroll
            for (int c = 0; c < C_; c++) acc[r][c] = fmaf(hv, w[c], acc[r][c]);
        }
    }
    #pragma unroll
    for (int r = 0; r < 4; r++) {
        float s = 0.f;
        #pragma unroll
        for (int c = 0; c < C_; c++) {
            double v = (double)acc[r][c];
            #pragma unroll
            for (int off = 16; off; off >>= 1)
                v += __shfl_down_sync(0xffffffffu, v, off);
            if (lane == 0) {
                float cf = fmaxf((float)v, 0.f);
                cas[(size_t)(m0 + r) * C_ + c] = cf;
                s = __fadd_rn(s, cf);
            }
        }
        if (lane == 0) act[m0 + r] = s;
    }
}

// ============================================================
__device__ __forceinline__ void bitonic_sort_desc(float* val, int* idx, int tid) {
    for (int k = 2; k <= 1024; k <<= 1) {
        for (int j = k >> 1; j > 0; j >>= 1) {
            int p = tid ^ j;
            if (p > tid) {
                float v1 = val[tid], v2 = val[p];
                int i1 = idx[tid], i2 = idx[p];
                bool dirFwd = ((tid & k) == 0);
                bool p_before = (v2 > v1) || (v2 == v1 && i2 < i1);
                if (p_before == dirFwd) {
                    val[tid] = v2; val[p] = v1;
                    idx[tid] = i2; idx[p] = i1;
                }
            }
            __syncthreads();
        }
    }
}

__global__ __launch_bounds__(1024) void batch_topk(const float* __restrict__ act) {
    __shared__ float s_act[T_];
    __shared__ float s_bin[T_];
    __shared__ float s_val[1024];
    __shared__ int   s_idx[1024];
    __shared__ float s_med, s_max;

    const int b = blockIdx.x, tid = threadIdx.x;
    const float NEG = -CUDART_INF_F;

    if (tid < T_) s_act[tid] = act[b * T_ + tid];
    __syncthreads();

    s_val[tid] = (tid < T_) ? s_act[tid] : NEG;
    __syncthreads();
    for (int off = 512; off; off >>= 1) {
        if (tid < off) s_val[tid] = fmaxf(s_val[tid], s_val[tid + off]);
        __syncthreads();
    }
    if (tid == 0) s_max = s_val[0];
    __syncthreads();

    s_val[tid] = (tid < T_) ? s_act[tid] : NEG;
    s_idx[tid] = (tid < T_) ? tid : (1 << 20);
    __syncthreads();
    bitonic_sort_desc(s_val, s_idx, tid);
    if (tid < K_EASY) g_idx[b * K_EASY + tid] = s_idx[tid];
    if (tid == 0) s_med = 0.5f * (s_val[374] + s_val[375]);
    __syncthreads();

    s_val[tid] = (tid < T_) ? __fsub_rn(s_max, s_act[tid]) : NEG;
    s_idx[tid] = (tid < T_) ? tid : (1 << 20);
    __syncthreads();
    bitonic_sort_desc(s_val, s_idx, tid);
    if (tid < K_EASY) g_idx[B_ * K_EASY + b * K_EASY + tid] = s_idx[tid];
    __syncthreads();

    if (tid < T_) s_bin[tid] = (s_act[tid] > s_med) ? 1.0f : 0.0f;
    __syncthreads();

    float sc = NEG;
    if (tid < T_) {
        float e3 = 1.f, e6 = 1.f;
        #pragma unroll
        for (int u = -1; u <= 1; u++) {
            int q = tid + u;
            e3 = fminf(e3, (q >= 0 && q < T_) ? s_bin[q] : 0.f);
        }
        #pragma unroll
        for (int u = -3; u <= 2; u++) {
            int q = tid + u;
            e6 = fminf(e6, (q >= 0 && q < T_) ? s_bin[q] : 0.f);
        }
        sc = s_act[tid] * (e3 - e6);
    }
    s_val[tid] = (tid < T_) ? sc : NEG;
    s_idx[tid] = (tid < T_) ? tid : (1 << 20);
    __syncthreads();
    bitonic_sort_desc(s_val, s_idx, tid);
    if (tid < K_HARD) g_idx[2 * B_ * K_EASY + b * K_HARD + tid] = s_idx[tid];
    __syncthreads();

    sc = NEG;
    if (tid < T_) {
        float d3 = 0.f, d6 = 0.f;
        #pragma unroll
        for (int u = -1; u <= 1; u++) {
            int q = tid + u;
            d3 = fmaxf(d3, (q >= 0 && q < T_) ? s_bin[q] : 0.f);
        }
        #pragma unroll
        for (int u = -2; u <= 3; u++) {
            int q = tid + u;
            d6 = fmaxf(d6, (q >= 0 && q < T_) ? s_bin[q] : 0.f);
        }
        sc = s_act[tid] * (d6 - d3);
    }
    s_val[tid] = (tid < T_) ? sc : NEG;
    s_idx[tid] = (tid < T_) ? tid : (1 << 20);
    __syncthreads();
    bitonic_sort_desc(s_val, s_idx, tid);
    if (tid < K_HARD)
        g_idx[2 * B_ * K_EASY + B_ * K_HARD + b * K_HARD + tid] = s_idx[tid];
}

__global__ __launch_bounds__(1024) void video_topk(const float* __restrict__ cas) {
    __shared__ float s_val[1024];
    __shared__ int   s_idx[1024];
    __shared__ float red[32];
    int bc = blockIdx.x;
    int b = bc / C_, c = bc - b * C_;
    int tid = threadIdx.x;
    s_val[tid] = (tid < T_) ? cas[(size_t)(b * T_ + tid) * C_ + c] : -CUDART_INF_F;
    s_idx[tid] = tid;
    __syncthreads();
    bitonic_sort_desc(s_val, s_idx, tid);
    float v = (tid < K_EASY) ? s_val[tid] : 0.f;
    #pragma unroll
    for (int off = 16; off; off >>= 1) v += __shfl_down_sync(0xffffffffu, v, off);
    if ((tid & 31) == 0) red[tid >> 5] = v;
    __syncthreads();
    if (tid < 32) {
        float t = red[tid];
        #pragma unroll
        for (int off = 16; off; off >>= 1) t += __shfl_down_sync(0xffffffffu, t, off);
        if (tid == 0) g_means[b * C_ + c] = t / (float)K_EASY;
    }
}

__global__ void softmax_k(float* __restrict__ out) {
    int b = blockIdx.x;
    int lane = threadIdx.x;
    float v = (lane < C_) ? g_means[b * C_ + lane] : -CUDART_INF_F;
    float mx = v;
    #pragma unroll
    for (int off = 16; off; off >>= 1) mx = fmaxf(mx, __shfl_xor_sync(0xffffffffu, mx, off));
    float e = (lane < C_) ? expf(v - mx) : 0.f;
    float s = e;
    #pragma unroll
    for (int off = 16; off; off >>= 1) s += __shfl_xor_sync(0xffffffffu, s, off);
    if (lane < C_) out[b * C_ + lane] = e / s;
}

__global__ __launch_bounds__(256) void gather_k(float* __restrict__ out) {
    int r = blockIdx.x;
    int b, t;
    size_t dst;
    if (r < B_ * K_EASY) {
        b = r / K_EASY; t = g_idx[r];
        dst = OFF_EA + (size_t)r * D_;
    } else if (r < 2 * B_ * K_EASY) {
        int rr = r - B_ * K_EASY;
        b = rr / K_EASY; t = g_idx[r];
        dst = OFF_EB + (size_t)rr * D_;
    } else if (r < 2 * B_ * K_EASY + B_ * K_HARD) {
        int rr = r - 2 * B_ * K_EASY;
        b = rr / K_HARD; t = g_idx[r];
        dst = OFF_HA + (size_t)rr * D_;
    } else {
        int rr = r - 2 * B_ * K_EASY - B_ * K_HARD;
        b = rr / K_HARD; t = g_idx[r];
        dst = OFF_HB + (size_t)rr * D_;
    }
    const float4* src = (const float4*)(g_h + ((size_t)(b * T_ + t) << 11));
    float4* d = (float4*)(out + dst);
    for (int i = threadIdx.x; i < D_ / 4; i += blockDim.x) d[i] = src[i];
}

// ============================================================
extern "C" void kernel_launch(void* const* d_in, const int* in_sizes, int n_in,
                              void* d_out, int out_size) {
    const float* x  = (const float*)d_in[0];
    const float* w1 = (const float*)d_in[1];
    const float* b1 = (const float*)d_in[2];
    const float* w2 = (const float*)d_in[3];
    float* out = (float*)d_out;

    cudaFuncSetAttribute(conv1_f16, cudaFuncAttributeMaxDynamicSharedMemorySize, DSMEM);

    pad_split_x<<<(B_ * 752 * (D_ / 4) + 255) / 256, 256>>>(x);
    {
        size_t tot = (size_t)D_ * K_DIM;
        split_w<<<(unsigned)((tot + 255) / 256), 256>>>(w1);
    }
    repack_w2_k<<<(D_ * C_ + 255) / 256, 256>>>(w2);
    {
        dim3 g(D_ / 64, (M_TOTAL + 127) / 128);   // (32, 94)
        conv1_f16<<<g, 256, DSMEM>>>(b1);
    }
    cas_kernel<<<(M_TOTAL / 4 + 7) / 8, 256>>>(out + OFF_CAS, out + OFF_ACT);
    batch_topk<<<B_, 1024>>>(out + OFF_ACT);
    video_topk<<<B_ * C_, 1024>>>(out + OFF_CAS);
    softmax_k<<<B_, 32>>>(out + OFF_VS);
    gather_k<<<2 * B_ * K_EASY + 2 * B_ * K_HARD, 256>>>(out);
}

// round 15
// speedup vs baseline: 1.0717x; 1.0227x over previous
#include <cuda_runtime.h>
#include <cuda_fp16.h>
#include <math_constants.h>
#include <cstddef>
#include <cstdint>

#define B_  16
#define T_  750
#define D_  2048
#define C_  20
constexpr int M_TOTAL = B_ * T_;     // 12000
constexpr int K_DIM   = 3 * D_;      // 6144
constexpr int K_EASY  = T_ / 5;      // 150
constexpr int K_HARD  = T_ / 20;     // 37

// ---- output offsets ----
constexpr size_t OFF_VS  = 0;
constexpr size_t OFF_EA  = OFF_VS + (size_t)B_ * C_;
constexpr size_t OFF_EB  = OFF_EA + (size_t)B_ * K_EASY * D_;
constexpr size_t OFF_HA  = OFF_EB + (size_t)B_ * K_EASY * D_;
constexpr size_t OFF_HB  = OFF_HA + (size_t)B_ * K_HARD * D_;
constexpr size_t OFF_ACT = OFF_HB + (size_t)B_ * K_HARD * D_;
constexpr size_t OFF_CAS = OFF_ACT + (size_t)B_ * T_;

// ---- scratch ----
__device__ __half g_xh[(size_t)B_ * 752 * D_];   // padded x hi
__device__ __half g_xl[(size_t)B_ * 752 * D_];   // padded x lo
__device__ __half g_wh[(size_t)D_ * K_DIM];      // (64*w1) hi, [n][ko*2048+io]
__device__ __half g_wl[(size_t)D_ * K_DIM];      // (64*w1) lo
__device__ float  g_w2t[D_ * C_];
__device__ float  g_h[(size_t)M_TOTAL * D_];
__device__ int    g_idx[2 * (B_ * K_EASY) + 2 * (B_ * K_HARD)];
__device__ float  g_means[B_ * C_];

// ============================================================
__global__ void pad_split_x(const float* __restrict__ x) {
    int idx = blockIdx.x * blockDim.x + threadIdx.x;
    const int per_b = 752 * (D_ / 4);
    if (idx >= B_ * per_b) return;
    int b  = idx / per_b;
    int r  = idx - b * per_b;
    int t  = r >> 9;
    int d4 = r & 511;
    float4 v = make_float4(0.f, 0.f, 0.f, 0.f);
    if (t >= 1 && t <= T_) {
        v = ((const float4*)x)[((size_t)(b * T_ + (t - 1)) << 9) + d4];
    }
    __half h[4], l[4];
    float f[4] = {v.x, v.y, v.z, v.w};
    #pragma unroll
    for (int i = 0; i < 4; i++) {
        h[i] = __float2half_rn(f[i]);
        l[i] = __float2half_rn(__fsub_rn(f[i], __half2float(h[i])));
    }
    *(uint2*)(g_xh + (size_t)idx * 4) = *(uint2*)h;
    *(uint2*)(g_xl + (size_t)idx * 4) = *(uint2*)l;
}

__global__ void split_w(const float* __restrict__ w1) {
    size_t i = (size_t)blockIdx.x * blockDim.x + threadIdx.x;
    if (i >= (size_t)D_ * K_DIM) return;
    int n  = (int)(i / K_DIM);
    int kc = (int)(i - (size_t)n * K_DIM);
    int ko = kc >> 11;
    int io = kc & 2047;
    float v = w1[(size_t)n * K_DIM + io * 3 + ko] * 64.0f;
    __half h = __float2half_rn(v);
    __half l = __float2half_rn(__fsub_rn(v, __half2float(h)));
    g_wh[i] = h;
    g_wl[i] = l;
}

__global__ void repack_w2_k(const float* __restrict__ w2) {
    int o = blockIdx.x * blockDim.x + threadIdx.x;
    if (o >= D_ * C_) return;
    int d = o / C_, c = o - d * C_;
    g_w2t[o] = w2[(size_t)c * D_ + d];
}

// ============================================================
// conv1 GEMM: fp16 3-product. CTA 64x64, 128 thr (4 warps 2m x 2n,
// warp 32x32). k=32 stages (192), ring 2, 4 CTAs/SM (4 independent
// barrier domains -> smem/tensor phase decorrelation).
// ldmatrix (non-trans); fold every 4 stages (g=128).
// ============================================================
constexpr int NSTG = K_DIM / 32;      // 192 stages
constexpr int RSB  = 80;              // row stride bytes (64 data + 16 pad)
constexpr int A_RB = 64 * RSB;        // 5120
constexpr int B_RB = 64 * RSB;        // 5120
constexpr int OFF_AH_S = 0;
constexpr int OFF_AL_S = A_RB;
constexpr int OFF_BH_S = 2 * A_RB;
constexpr int OFF_BL_S = 2 * A_RB + B_RB;
constexpr int STAGE_B = 2 * A_RB + 2 * B_RB;   // 20480
constexpr int RING = 2;
constexpr int DIST = 1;
constexpr int DSMEM = RING * STAGE_B;          // 40960

#define CP16(dst, src) \
    asm volatile("cp.async.cg.shared.global [%0], [%1], 16;" :: "r"(dst), "l"(src))
#define CP_COMMIT() asm volatile("cp.async.commit_group;" ::: "memory")
#define CP_WAIT0()  asm volatile("cp.async.wait_group 0;" ::: "memory")

#define MMA_F16(c, a0, a1, a2, a3, b0, b1) \
    asm("mma.sync.aligned.m16n8k16.row.col.f32.f16.f16.f32 " \
        "{%0,%1,%2,%3}, {%4,%5,%6,%7}, {%8,%9}, {%0,%1,%2,%3};" \
        : "+f"((c)[0]), "+f"((c)[1]), "+f"((c)[2]), "+f"((c)[3]) \
        : "r"(a0), "r"(a1), "r"(a2), "r"(a3), "r"(b0), "r"(b1))

#define LDSM4(r0, r1, r2, r3, addr) \
    asm volatile("ldmatrix.sync.aligned.m8n8.x4.shared.b16 {%0,%1,%2,%3}, [%4];" \
        : "=r"(r0), "=r"(r1), "=r"(r2), "=r"(r3) : "r"(addr))

__device__ __forceinline__ uint32_t smem_u32(const void* p) {
    uint32_t a;
    asm("{ .reg .u64 t; cvta.to.shared.u64 t, %1; cvt.u32.u64 %0, t; }" : "=r"(a) : "l"(p));
    return a;
}

__global__ __launch_bounds__(128, 4) void conv1_f16(const float* __restrict__ b1) {
    extern __shared__ char dsm[];
    const uint32_t smb = smem_u32(dsm);

    const int tid  = threadIdx.x;
    const int lane = tid & 31;
    const int wid  = tid >> 5;       // 0..3
    const int wm   = wid & 1;        // m half (32 rows)
    const int wn   = wid >> 1;       // n half (32 cols)
    const int bn   = blockIdx.x;     // 0..31
    const int bm   = blockIdx.y;     // 0..187
    const int tig  = lane & 3;
    const int gid  = lane >> 2;

    // ---- copy mapping (per stage, 8 x CP16 per thread) ----
    // A region: 64 rows x 64B; thread t covers row t>>1, 32B at (t&1)*32.
    // B region: same geometry.
    const int arow  = tid >> 1;           // 0..63
    const int aoffB = (tid & 1) * 32;
    int mA = bm * 64 + arow;
    int mcA = (mA < M_TOTAL) ? mA : 0;
    int bbA = mcA / T_, ttA = mcA - bbA * T_;
    const __half* srcAh = g_xh + (((size_t)(bbA * 752 + ttA)) << 11) + aoffB / 2;
    const __half* srcAl = g_xl + (((size_t)(bbA * 752 + ttA)) << 11) + aoffB / 2;
    const __half* srcBh = g_wh + (size_t)(bn * 64 + arow) * K_DIM + aoffB / 2;
    const __half* srcBl = g_wl + (size_t)(bn * 64 + arow) * K_DIM + aoffB / 2;
    const uint32_t dstR = (uint32_t)(arow * RSB + aoffB);

    // ldmatrix lane-address components (non-trans for both A and B)
    const int aLRow = lane & 15;                         // A: row within 16
    const int aLK   = (lane >> 4) << 4;                  // A: k-chunk byte (0/16)
    const int bLRow = (lane & 7) + ((lane >> 4) << 3);   // B: n-row within 16
    const int bLK   = ((lane >> 3) & 1) << 4;            // B: k-chunk byte (0/16)

    float acc[2][4][4], cfr[2][4][4];
    #pragma unroll
    for (int i = 0; i < 2; i++)
        #pragma unroll
        for (int j = 0; j < 4; j++)
            #pragma unroll
            for (int q = 0; q < 4; q++) { acc[i][j][q] = 0.f; cfr[i][j][q] = 0.f; }

    // prologue: stage 0 -> buf 0
    {
        uint32_t bp = smb;
        CP16(bp + OFF_AH_S + dstR,      srcAh);
        CP16(bp + OFF_AH_S + dstR + 16, srcAh + 8);
        CP16(bp + OFF_AL_S + dstR,      srcAl);
        CP16(bp + OFF_AL_S + dstR + 16, srcAl + 8);
        CP16(bp + OFF_BH_S + dstR,      srcBh);
        CP16(bp + OFF_BH_S + dstR + 16, srcBh + 8);
        CP16(bp + OFF_BL_S + dstR,      srcBl);
        CP16(bp + OFF_BL_S + dstR + 16, srcBl + 8);
        CP_COMMIT();
    }

    #pragma unroll 1
    for (int s = 0; s < NSTG; s++) {
        const int q = s & 1;
        CP_WAIT0();
        __syncthreads();
        if (s + DIST < NSTG) {
            uint32_t bq = smb + (q ^ 1) * STAGE_B;
            const size_t ko = (size_t)(s + DIST) * 32;
            CP16(bq + OFF_AH_S + dstR,      srcAh + ko);
            CP16(bq + OFF_AH_S + dstR + 16, srcAh + ko + 8);
            CP16(bq + OFF_AL_S + dstR,      srcAl + ko);
            CP16(bq + OFF_AL_S + dstR + 16, srcAl + ko + 8);
            CP16(bq + OFF_BH_S + dstR,      srcBh + ko);
            CP16(bq + OFF_BH_S + dstR + 16, srcBh + ko + 8);
            CP16(bq + OFF_BL_S + dstR,      srcBl + ko);
            CP16(bq + OFF_BL_S + dstR + 16, srcBl + ko + 8);
        }
        CP_COMMIT();   // one group per iter (empty in tail)

        const uint32_t stU = smb + q * STAGE_B;
        #pragma unroll
        for (int u = 0; u < 2; u++) {
            // B fragments via ldmatrix.x4 (2 nt per instruction)
            uint32_t bh[4][2], bl[4][2];
            #pragma unroll
            for (int p = 0; p < 2; p++) {
                int n0 = wn * 32 + p * 16;
                uint32_t ad  = stU + OFF_BH_S + (uint32_t)((n0 + bLRow) * RSB + u * 32 + bLK);
                LDSM4(bh[2*p][0], bh[2*p][1], bh[2*p+1][0], bh[2*p+1][1], ad);
                uint32_t adl = stU + OFF_BL_S + (uint32_t)((n0 + bLRow) * RSB + u * 32 + bLK);
                LDSM4(bl[2*p][0], bl[2*p][1], bl[2*p+1][0], bl[2*p+1][1], adl);
            }
            // A fragments via ldmatrix.x4
            uint32_t ah[2][4], al[2][4];
            #pragma unroll
            for (int mt = 0; mt < 2; mt++) {
                int rb = wm * 32 + mt * 16;
                uint32_t ad  = stU + OFF_AH_S + (uint32_t)((rb + aLRow) * RSB + u * 32 + aLK);
                LDSM4(ah[mt][0], ah[mt][1], ah[mt][2], ah[mt][3], ad);
                uint32_t adl = stU + OFF_AL_S + (uint32_t)((rb + aLRow) * RSB + u * 32 + aLK);
                LDSM4(al[mt][0], al[mt][1], al[mt][2], al[mt][3], adl);
            }
            #pragma unroll
            for (int mt = 0; mt < 2; mt++)
                #pragma unroll
                for (int nt = 0; nt < 4; nt++) {
                    MMA_F16(cfr[mt][nt], ah[mt][0], ah[mt][1], ah[mt][2], ah[mt][3],
                            bh[nt][0], bh[nt][1]);
                    MMA_F16(cfr[mt][nt], al[mt][0], al[mt][1], al[mt][2], al[mt][3],
                            bh[nt][0], bh[nt][1]);
                    MMA_F16(cfr[mt][nt], ah[mt][0], ah[mt][1], ah[mt][2], ah[mt][3],
                            bl[nt][0], bl[nt][1]);
                }
        }

        // fold every 4 stages (g = 128 k terms): 2Sum; comp rides in cfr
        if ((s & 3) == 3) {
            #pragma unroll
            for (int mt = 0; mt < 2; mt++)
                #pragma unroll
                for (int nt = 0; nt < 4; nt++)
                    #pragma unroll
                    for (int qq = 0; qq < 4; qq++) {
                        float a = acc[mt][nt][qq], c = cfr[mt][nt][qq];
                        float sP = __fadd_rn(a, c);
                        float bb2 = __fsub_rn(sP, a);
                        float err = __fadd_rn(__fsub_rn(a, __fsub_rn(sP, bb2)),
                                              __fsub_rn(c, bb2));
                        acc[mt][nt][qq] = sP;
                        cfr[mt][nt][qq] = err;
                    }
        }
    }

    // epilogue: unscale 2^-6, + bias, relu -> g_h
    #pragma unroll
    for (int mt = 0; mt < 2; mt++) {
        #pragma unroll
        for (int r2 = 0; r2 < 2; r2++) {
            int m = bm * 64 + wm * 32 + mt * 16 + gid + r2 * 8;
            if (m < M_TOTAL) {
                #pragma unroll
                for (int nt = 0; nt < 4; nt++) {
                    int n = bn * 64 + wn * 32 + nt * 8 + tig * 2;
                    float s0 = __fadd_rn(acc[mt][nt][r2*2+0], cfr[mt][nt][r2*2+0]) * 0.015625f;
                    float s1 = __fadd_rn(acc[mt][nt][r2*2+1], cfr[mt][nt][r2*2+1]) * 0.015625f;
                    float v0 = fmaxf(__fadd_rn(s0, b1[n]), 0.f);
                    float v1 = fmaxf(__fadd_rn(s1, b1[n+1]), 0.f);
                    *(float2*)(g_h + (size_t)m * D_ + n) = make_float2(v0, v1);
                }
            }
        }
    }
}

// ============================================================
// cas + actionness (unchanged)
// ============================================================
__global__ __launch_bounds__(256) void cas_kernel(float* __restrict__ cas,
                                                  float* __restrict__ act) {
    int warp = blockIdx.x * 8 + (threadIdx.x >> 5);
    int lane = threadIdx.x & 31;
    int m0 = warp * 4;
    if (m0 >= M_TOTAL) return;

    float acc[4][20];
    #pragma unroll
    for (int r = 0; r < 4; r++)
        #pragma unroll
        for (int c = 0; c < C_; c++) acc[r][c] = 0.f;

    for (int d = lane; d < D_; d += 32) {
        float w[20];
        const float4* wp = (const float4*)(g_w2t + d * C_);
        #pragma unroll
        for (int q = 0; q < 5; q++) {
            float4 t4 = wp[q];
            w[q * 4 + 0] = t4.x; w[q * 4 + 1] = t4.y;
            w[q * 4 + 2] = t4.z; w[q * 4 + 3] = t4.w;
        }
        #pragma unroll
        for (int r = 0; r < 4; r++) {
            float hv = g_h[(size_t)(m0 + r) * D_ + d];
            #pragma unroll
            for (int c = 0; c < C_; c++) acc[r][c] = fmaf(hv, w[c], acc[r][c]);
        }
    }
    #pragma unroll
    for (int r = 0; r < 4; r++) {
        float s = 0.f;
        #pragma unroll
        for (int c = 0; c < C_; c++) {
            double v = (double)acc[r][c];
            #pragma unroll
            for (int off = 16; off; off >>= 1)
                v += __shfl_down_sync(0xffffffffu, v, off);
            if (lane == 0) {
                float cf = fmaxf((float)v, 0.f);
                cas[(size_t)(m0 + r) * C_ + c] = cf;
                s = __fadd_rn(s, cf);
            }
        }
        if (lane == 0) act[m0 + r] = s;
    }
}

// ============================================================
__device__ __forceinline__ void bitonic_sort_desc(float* val, int* idx, int tid) {
    for (int k = 2; k <= 1024; k <<= 1) {
        for (int j = k >> 1; j > 0; j >>= 1) {
            int p = tid ^ j;
            if (p > tid) {
                float v1 = val[tid], v2 = val[p];
                int i1 = idx[tid], i2 = idx[p];
                bool dirFwd = ((tid & k) == 0);
                bool p_before = (v2 > v1) || (v2 == v1 && i2 < i1);
                if (p_before == dirFwd) {
                    val[tid] = v2; val[p] = v1;
                    idx[tid] = i2; idx[p] = i1;
                }
            }
            __syncthreads();
        }
    }
}

__global__ __launch_bounds__(1024) void batch_topk(const float* __restrict__ act) {
    __shared__ float s_act[T_];
    __shared__ float s_bin[T_];
    __shared__ float s_val[1024];
    __shared__ int   s_idx[1024];
    __shared__ float s_med, s_max;

    const int b = blockIdx.x, tid = threadIdx.x;
    const float NEG = -CUDART_INF_F;

    if (tid < T_) s_act[tid] = act[b * T_ + tid];
    __syncthreads();

    s_val[tid] = (tid < T_) ? s_act[tid] : NEG;
    __syncthreads();
    for (int off = 512; off; off >>= 1) {
        if (tid < off) s_val[tid] = fmaxf(s_val[tid], s_val[tid + off]);
        __syncthreads();
    }
    if (tid == 0) s_max = s_val[0];
    __syncthreads();

    s_val[tid] = (tid < T_) ? s_act[tid] : NEG;
    s_idx[tid] = (tid < T_) ? tid : (1 << 20);
    __syncthreads();
    bitonic_sort_desc(s_val, s_idx, tid);
    if (tid < K_EASY) g_idx[b * K_EASY + tid] = s_idx[tid];
    if (tid == 0) s_med = 0.5f * (s_val[374] + s_val[375]);
    __syncthreads();

    s_val[tid] = (tid < T_) ? __fsub_rn(s_max, s_act[tid]) : NEG;
    s_idx[tid] = (tid < T_) ? tid : (1 << 20);
    __syncthreads();
    bitonic_sort_desc(s_val, s_idx, tid);
    if (tid < K_EASY) g_idx[B_ * K_EASY + b * K_EASY + tid] = s_idx[tid];
    __syncthreads();

    if (tid < T_) s_bin[tid] = (s_act[tid] > s_med) ? 1.0f : 0.0f;
    __syncthreads();

    float sc = NEG;
    if (tid < T_) {
        float e3 = 1.f, e6 = 1.f;
        #pragma unroll
        for (int u = -1; u <= 1; u++) {
            int q = tid + u;
            e3 = fminf(e3, (q >= 0 && q < T_) ? s_bin[q] : 0.f);
        }
        #pragma unroll
        for (int u = -3; u <= 2; u++) {
            int q = tid + u;
            e6 = fminf(e6, (q >= 0 && q < T_) ? s_bin[q] : 0.f);
        }
        sc = s_act[tid] * (e3 - e6);
    }
    s_val[tid] = (tid < T_) ? sc : NEG;
    s_idx[tid] = (tid < T_) ? tid : (1 << 20);
    __syncthreads();
    bitonic_sort_desc(s_val, s_idx, tid);
    if (tid < K_HARD) g_idx[2 * B_ * K_EASY + b * K_HARD + tid] = s_idx[tid];
    __syncthreads();

    sc = NEG;
    if (tid < T_) {
        float d3 = 0.f, d6 = 0.f;
        #pragma unroll
        for (int u = -1; u <= 1; u++) {
            int q = tid + u;
            d3 = fmaxf(d3, (q >= 0 && q < T_) ? s_bin[q] : 0.f);
        }
        #pragma unroll
        for (int u = -2; u <= 3; u++) {
            int q = tid + u;
            d6 = fmaxf(d6, (q >= 0 && q < T_) ? s_bin[q] : 0.f);
        }
        sc = s_act[tid] * (d6 - d3);
    }
    s_val[tid] = (tid < T_) ? sc : NEG;
    s_idx[tid] = (tid < T_) ? tid : (1 << 20);
    __syncthreads();
    bitonic_sort_desc(s_val, s_idx, tid);
    if (tid < K_HARD)
        g_idx[2 * B_ * K_EASY + B_ * K_HARD + b * K_HARD + tid] = s_idx[tid];
}

__global__ __launch_bounds__(1024) void video_topk(const float* __restrict__ cas) {
    __shared__ float s_val[1024];
    __shared__ int   s_idx[1024];
    __shared__ float red[32];
    int bc = blockIdx.x;
    int b = bc / C_, c = bc - b * C_;
    int tid = threadIdx.x;
    s_val[tid] = (tid < T_) ? cas[(size_t)(b * T_ + tid) * C_ + c] : -CUDART_INF_F;
    s_idx[tid] = tid;
    __syncthreads();
    bitonic_sort_desc(s_val, s_idx, tid);
    float v = (tid < K_EASY) ? s_val[tid] : 0.f;
    #pragma unroll
    for (int off = 16; off; off >>= 1) v += __shfl_down_sync(0xffffffffu, v, off);
    if ((tid & 31) == 0) red[tid >> 5] = v;
    __syncthreads();
    if (tid < 32) {
        float t = red[tid];
        #pragma unroll
        for (int off = 16; off; off >>= 1) t += __shfl_down_sync(0xffffffffu, t, off);
        if (tid == 0) g_means[b * C_ + c] = t / (float)K_EASY;
    }
}

__global__ void softmax_k(float* __restrict__ out) {
    int b = blockIdx.x;
    int lane = threadIdx.x;
    float v = (lane < C_) ? g_means[b * C_ + lane] : -CUDART_INF_F;
    float mx = v;
    #pragma unroll
    for (int off = 16; off; off >>= 1) mx = fmaxf(mx, __shfl_xor_sync(0xffffffffu, mx, off));
    float e = (lane < C_) ? expf(v - mx) : 0.f;
    float s = e;
    #pragma unroll
    for (int off = 16; off; off >>= 1) s += __shfl_xor_sync(0xffffffffu, s, off);
    if (lane < C_) out[b * C_ + lane] = e / s;
}

__global__ __launch_bounds__(256) void gather_k(float* __restrict__ out) {
    int r = blockIdx.x;
    int b, t;
    size_t dst;
    if (r < B_ * K_EASY) {
        b = r / K_EASY; t = g_idx[r];
        dst = OFF_EA + (size_t)r * D_;
    } else if (r < 2 * B_ * K_EASY) {
        int rr = r - B_ * K_EASY;
        b = rr / K_EASY; t = g_idx[r];
        dst = OFF_EB + (size_t)rr * D_;
    } else if (r < 2 * B_ * K_EASY + B_ * K_HARD) {
        int rr = r - 2 * B_ * K_EASY;
        b = rr / K_HARD; t = g_idx[r];
        dst = OFF_HA + (size_t)rr * D_;
    } else {
        int rr = r - 2 * B_ * K_EASY - B_ * K_HARD;
        b = rr / K_HARD; t = g_idx[r];
        dst = OFF_HB + (size_t)rr * D_;
    }
    const float4* src = (const float4*)(g_h + ((size_t)(b * T_ + t) << 11));
    float4* d = (float4*)(out + dst);
    for (int i = threadIdx.x; i < D_ / 4; i += blockDim.x) d[i] = src[i];
}

// ============================================================
extern "C" void kernel_launch(void* const* d_in, const int* in_sizes, int n_in,
                              void* d_out, int out_size) {
    const float* x  = (const float*)d_in[0];
    const float* w1 = (const float*)d_in[1];
    const float* b1 = (const float*)d_in[2];
    const float* w2 = (const float*)d_in[3];
    float* out = (float*)d_out;

    cudaFuncSetAttribute(conv1_f16, cudaFuncAttributeMaxDynamicSharedMemorySize, DSMEM);

    pad_split_x<<<(B_ * 752 * (D_ / 4) + 255) / 256, 256>>>(x);
    {
        size_t tot = (size_t)D_ * K_DIM;
        split_w<<<(unsigned)((tot + 255) / 256), 256>>>(w1);
    }
    repack_w2_k<<<(D_ * C_ + 255) / 256, 256>>>(w2);
    {
        dim3 g(D_ / 64, (M_TOTAL + 63) / 64);   // (32, 188)
        conv1_f16<<<g, 128, DSMEM>>>(b1);
    }
    cas_kernel<<<(M_TOTAL / 4 + 7) / 8, 256>>>(out + OFF_CAS, out + OFF_ACT);
    batch_topk<<<B_, 1024>>>(out + OFF_ACT);
    video_topk<<<B_ * C_, 1024>>>(out + OFF_CAS);
    softmax_k<<<B_, 32>>>(out + OFF_VS);
    gather_k<<<2 * B_ * K_EASY + 2 * B_ * K_HARD, 256>>>(out);
}

// round 16
// speedup vs baseline: 1.0833x; 1.0107x over previous
#include <cuda_runtime.h>
#include <cuda_fp16.h>
#include <math_constants.h>
#include <cstddef>
#include <cstdint>

#define B_  16
#define T_  750
#define D_  2048
#define C_  20
constexpr int M_TOTAL = B_ * T_;     // 12000
constexpr int K_DIM   = 3 * D_;      // 6144
constexpr int K_EASY  = T_ / 5;      // 150
constexpr int K_HARD  = T_ / 20;     // 37

// ---- output offsets ----
constexpr size_t OFF_VS  = 0;
constexpr size_t OFF_EA  = OFF_VS + (size_t)B_ * C_;
constexpr size_t OFF_EB  = OFF_EA + (size_t)B_ * K_EASY * D_;
constexpr size_t OFF_HA  = OFF_EB + (size_t)B_ * K_EASY * D_;
constexpr size_t OFF_HB  = OFF_HA + (size_t)B_ * K_HARD * D_;
constexpr size_t OFF_ACT = OFF_HB + (size_t)B_ * K_HARD * D_;
constexpr size_t OFF_CAS = OFF_ACT + (size_t)B_ * T_;

// ---- scratch ----
__device__ __half g_xh[(size_t)B_ * 752 * D_];   // padded x hi
__device__ __half g_xl[(size_t)B_ * 752 * D_];   // padded x lo
__device__ __half g_wh[(size_t)D_ * K_DIM];      // (64*w1) hi, [n][ko*2048+io]
__device__ __half g_wl[(size_t)D_ * K_DIM];      // (64*w1) lo
__device__ float  g_w2t[D_ * C_];
__device__ float  g_h[(size_t)M_TOTAL * D_];
__device__ int    g_idx[2 * (B_ * K_EASY) + 2 * (B_ * K_HARD)];
__device__ float  g_means[B_ * C_];

// ============================================================
__global__ void pad_split_x(const float* __restrict__ x) {
    int idx = blockIdx.x * blockDim.x + threadIdx.x;
    const int per_b = 752 * (D_ / 4);
    if (idx >= B_ * per_b) return;
    int b  = idx / per_b;
    int r  = idx - b * per_b;
    int t  = r >> 9;
    int d4 = r & 511;
    float4 v = make_float4(0.f, 0.f, 0.f, 0.f);
    if (t >= 1 && t <= T_) {
        v = ((const float4*)x)[((size_t)(b * T_ + (t - 1)) << 9) + d4];
    }
    __half h[4], l[4];
    float f[4] = {v.x, v.y, v.z, v.w};
    #pragma unroll
    for (int i = 0; i < 4; i++) {
        h[i] = __float2half_rn(f[i]);
        l[i] = __float2half_rn(__fsub_rn(f[i], __half2float(h[i])));
    }
    *(uint2*)(g_xh + (size_t)idx * 4) = *(uint2*)h;
    *(uint2*)(g_xl + (size_t)idx * 4) = *(uint2*)l;
}

__global__ void split_w(const float* __restrict__ w1) {
    size_t i = (size_t)blockIdx.x * blockDim.x + threadIdx.x;
    if (i >= (size_t)D_ * K_DIM) return;
    int n  = (int)(i / K_DIM);
    int kc = (int)(i - (size_t)n * K_DIM);
    int ko = kc >> 11;
    int io = kc & 2047;
    float v = w1[(size_t)n * K_DIM + io * 3 + ko] * 64.0f;
    __half h = __float2half_rn(v);
    __half l = __float2half_rn(__fsub_rn(v, __half2float(h)));
    g_wh[i] = h;
    g_wl[i] = l;
}

__global__ void repack_w2_k(const float* __restrict__ w2) {
    int o = blockIdx.x * blockDim.x + threadIdx.x;
    if (o >= D_ * C_) return;
    int d = o / C_, c = o - d * C_;
    g_w2t[o] = w2[(size_t)c * D_ + d];
}

// ============================================================
// conv1 GEMM: fp16 3-product. CTA 64x64, 128 thr (4 warps 2m x 2n,
// warp 32x32). k=32 stages (192), ring 2, 4 CTAs/SM.
// ldmatrix (non-trans); fold every 8 stages (g=256).
// ============================================================
constexpr int NSTG = K_DIM / 32;      // 192 stages
constexpr int RSB  = 80;              // row stride bytes (64 data + 16 pad)
constexpr int A_RB = 64 * RSB;        // 5120
constexpr int B_RB = 64 * RSB;        // 5120
constexpr int OFF_AH_S = 0;
constexpr int OFF_AL_S = A_RB;
constexpr int OFF_BH_S = 2 * A_RB;
constexpr int OFF_BL_S = 2 * A_RB + B_RB;
constexpr int STAGE_B = 2 * A_RB + 2 * B_RB;   // 20480
constexpr int RING = 2;
constexpr int DIST = 1;
constexpr int DSMEM = RING * STAGE_B;          // 40960

#define CP16(dst, src) \
    asm volatile("cp.async.cg.shared.global [%0], [%1], 16;" :: "r"(dst), "l"(src))
#define CP_COMMIT() asm volatile("cp.async.commit_group;" ::: "memory")
#define CP_WAIT0()  asm volatile("cp.async.wait_group 0;" ::: "memory")

#define MMA_F16(c, a0, a1, a2, a3, b0, b1) \
    asm("mma.sync.aligned.m16n8k16.row.col.f32.f16.f16.f32 " \
        "{%0,%1,%2,%3}, {%4,%5,%6,%7}, {%8,%9}, {%0,%1,%2,%3};" \
        : "+f"((c)[0]), "+f"((c)[1]), "+f"((c)[2]), "+f"((c)[3]) \
        : "r"(a0), "r"(a1), "r"(a2), "r"(a3), "r"(b0), "r"(b1))

#define LDSM4(r0, r1, r2, r3, addr) \
    asm volatile("ldmatrix.sync.aligned.m8n8.x4.shared.b16 {%0,%1,%2,%3}, [%4];" \
        : "=r"(r0), "=r"(r1), "=r"(r2), "=r"(r3) : "r"(addr))

__device__ __forceinline__ uint32_t smem_u32(const void* p) {
    uint32_t a;
    asm("{ .reg .u64 t; cvta.to.shared.u64 t, %1; cvt.u32.u64 %0, t; }" : "=r"(a) : "l"(p));
    return a;
}

__global__ __launch_bounds__(128, 4) void conv1_f16(const float* __restrict__ b1) {
    extern __shared__ char dsm[];
    const uint32_t smb = smem_u32(dsm);

    const int tid  = threadIdx.x;
    const int lane = tid & 31;
    const int wid  = tid >> 5;       // 0..3
    const int wm   = wid & 1;        // m half (32 rows)
    const int wn   = wid >> 1;       // n half (32 cols)
    const int bn   = blockIdx.x;     // 0..31
    const int bm   = blockIdx.y;     // 0..187
    const int tig  = lane & 3;
    const int gid  = lane >> 2;

    // ---- copy mapping (per stage, 8 x CP16 per thread) ----
    const int arow  = tid >> 1;           // 0..63
    const int aoffB = (tid & 1) * 32;
    int mA = bm * 64 + arow;
    int mcA = (mA < M_TOTAL) ? mA : 0;
    int bbA = mcA / T_, ttA = mcA - bbA * T_;
    const __half* srcAh = g_xh + (((size_t)(bbA * 752 + ttA)) << 11) + aoffB / 2;
    const __half* srcAl = g_xl + (((size_t)(bbA * 752 + ttA)) << 11) + aoffB / 2;
    const __half* srcBh = g_wh + (size_t)(bn * 64 + arow) * K_DIM + aoffB / 2;
    const __half* srcBl = g_wl + (size_t)(bn * 64 + arow) * K_DIM + aoffB / 2;
    const uint32_t dstR = (uint32_t)(arow * RSB + aoffB);

    // ldmatrix lane-address components (non-trans for both A and B)
    const int aLRow = lane & 15;                         // A: row within 16
    const int aLK   = (lane >> 4) << 4;                  // A: k-chunk byte (0/16)
    const int bLRow = (lane & 7) + ((lane >> 4) << 3);   // B: n-row within 16
    const int bLK   = ((lane >> 3) & 1) << 4;            // B: k-chunk byte (0/16)

    float acc[2][4][4], cfr[2][4][4];
    #pragma unroll
    for (int i = 0; i < 2; i++)
        #pragma unroll
        for (int j = 0; j < 4; j++)
            #pragma unroll
            for (int q = 0; q < 4; q++) { acc[i][j][q] = 0.f; cfr[i][j][q] = 0.f; }

    // prologue: stage 0 -> buf 0
    {
        uint32_t bp = smb;
        CP16(bp + OFF_AH_S + dstR,      srcAh);
        CP16(bp + OFF_AH_S + dstR + 16, srcAh + 8);
        CP16(bp + OFF_AL_S + dstR,      srcAl);
        CP16(bp + OFF_AL_S + dstR + 16, srcAl + 8);
        CP16(bp + OFF_BH_S + dstR,      srcBh);
        CP16(bp + OFF_BH_S + dstR + 16, srcBh + 8);
        CP16(bp + OFF_BL_S + dstR,      srcBl);
        CP16(bp + OFF_BL_S + dstR + 16, srcBl + 8);
        CP_COMMIT();
    }

    #pragma unroll 1
    for (int s = 0; s < NSTG; s++) {
        const int q = s & 1;
        CP_WAIT0();
        __syncthreads();
        if (s + DIST < NSTG) {
            uint32_t bq = smb + (q ^ 1) * STAGE_B;
            const size_t ko = (size_t)(s + DIST) * 32;
            CP16(bq + OFF_AH_S + dstR,      srcAh + ko);
            CP16(bq + OFF_AH_S + dstR + 16, srcAh + ko + 8);
            CP16(bq + OFF_AL_S + dstR,      srcAl + ko);
            CP16(bq + OFF_AL_S + dstR + 16, srcAl + ko + 8);
            CP16(bq + OFF_BH_S + dstR,      srcBh + ko);
            CP16(bq + OFF_BH_S + dstR + 16, srcBh + ko + 8);
            CP16(bq + OFF_BL_S + dstR,      srcBl + ko);
            CP16(bq + OFF_BL_S + dstR + 16, srcBl + ko + 8);
        }
        CP_COMMIT();   // one group per iter (empty in tail)

        const uint32_t stU = smb + q * STAGE_B;
        #pragma unroll
        for (int u = 0; u < 2; u++) {
            // B fragments via ldmatrix.x4 (2 nt per instruction)
            uint32_t bh[4][2], bl[4][2];
            #pragma unroll
            for (int p = 0; p < 2; p++) {
                int n0 = wn * 32 + p * 16;
                uint32_t ad  = stU + OFF_BH_S + (uint32_t)((n0 + bLRow) * RSB + u * 32 + bLK);
                LDSM4(bh[2*p][0], bh[2*p][1], bh[2*p+1][0], bh[2*p+1][1], ad);
                uint32_t adl = stU + OFF_BL_S + (uint32_t)((n0 + bLRow) * RSB + u * 32 + bLK);
                LDSM4(bl[2*p][0], bl[2*p][1], bl[2*p+1][0], bl[2*p+1][1], adl);
            }
            // A fragments via ldmatrix.x4
            uint32_t ah[2][4], al[2][4];
            #pragma unroll
            for (int mt = 0; mt < 2; mt++) {
                int rb = wm * 32 + mt * 16;
                uint32_t ad  = stU + OFF_AH_S + (uint32_t)((rb + aLRow) * RSB + u * 32 + aLK);
                LDSM4(ah[mt][0], ah[mt][1], ah[mt][2], ah[mt][3], ad);
                uint32_t adl = stU + OFF_AL_S + (uint32_t)((rb + aLRow) * RSB + u * 32 + aLK);
                LDSM4(al[mt][0], al[mt][1], al[mt][2], al[mt][3], adl);
            }
            #pragma unroll
            for (int mt = 0; mt < 2; mt++)
                #pragma unroll
                for (int nt = 0; nt < 4; nt++) {
                    MMA_F16(cfr[mt][nt], ah[mt][0], ah[mt][1], ah[mt][2], ah[mt][3],
                            bh[nt][0], bh[nt][1]);
                    MMA_F16(cfr[mt][nt], al[mt][0], al[mt][1], al[mt][2], al[mt][3],
                            bh[nt][0], bh[nt][1]);
                    MMA_F16(cfr[mt][nt], ah[mt][0], ah[mt][1], ah[mt][2], ah[mt][3],
                            bl[nt][0], bl[nt][1]);
                }
        }

        // fold every 8 stages (g = 256 k terms): 2Sum; comp rides in cfr
        if ((s & 7) == 7) {
            #pragma unroll
            for (int mt = 0; mt < 2; mt++)
                #pragma unroll
                for (int nt = 0; nt < 4; nt++)
                    #pragma unroll
                    for (int qq = 0; qq < 4; qq++) {
                        float a = acc[mt][nt][qq], c = cfr[mt][nt][qq];
                        float sP = __fadd_rn(a, c);
                        float bb2 = __fsub_rn(sP, a);
                        float err = __fadd_rn(__fsub_rn(a, __fsub_rn(sP, bb2)),
                                              __fsub_rn(c, bb2));
                        acc[mt][nt][qq] = sP;
                        cfr[mt][nt][qq] = err;
                    }
        }
    }

    // epilogue: unscale 2^-6, + bias, relu -> g_h
    #pragma unroll
    for (int mt = 0; mt < 2; mt++) {
        #pragma unroll
        for (int r2 = 0; r2 < 2; r2++) {
            int m = bm * 64 + wm * 32 + mt * 16 + gid + r2 * 8;
            if (m < M_TOTAL) {
                #pragma unroll
                for (int nt = 0; nt < 4; nt++) {
                    int n = bn * 64 + wn * 32 + nt * 8 + tig * 2;
                    float s0 = __fadd_rn(acc[mt][nt][r2*2+0], cfr[mt][nt][r2*2+0]) * 0.015625f;
                    float s1 = __fadd_rn(acc[mt][nt][r2*2+1], cfr[mt][nt][r2*2+1]) * 0.015625f;
                    float v0 = fmaxf(__fadd_rn(s0, b1[n]), 0.f);
                    float v1 = fmaxf(__fadd_rn(s1, b1[n+1]), 0.f);
                    *(float2*)(g_h + (size_t)m * D_ + n) = make_float2(v0, v1);
                }
            }
        }
    }
}

// ============================================================
// cas + actionness (unchanged)
// ============================================================
__global__ __launch_bounds__(256) void cas_kernel(float* __restrict__ cas,
                                                  float* __restrict__ act) {
    int warp = blockIdx.x * 8 + (threadIdx.x >> 5);
    int lane = threadIdx.x & 31;
    int m0 = warp * 4;
    if (m0 >= M_TOTAL) return;

    float acc[4][20];
    #pragma unroll
    for (int r = 0; r < 4; r++)
        #pragma unroll
        for (int c = 0; c < C_; c++) acc[r][c] = 0.f;

    for (int d = lane; d < D_; d += 32) {
        float w[20];
        const float4* wp = (const float4*)(g_w2t + d * C_);
        #pragma unroll
        for (int q = 0; q < 5; q++) {
            float4 t4 = wp[q];
            w[q * 4 + 0] = t4.x; w[q * 4 + 1] = t4.y;
            w[q * 4 + 2] = t4.z; w[q * 4 + 3] = t4.w;
        }
        #pragma unroll
        for (int r = 0; r < 4; r++) {
            float hv = g_h[(size_t)(m0 + r) * D_ + d];
            #pragma unroll
            for (int c = 0; c < C_; c++) acc[r][c] = fmaf(hv, w[c], acc[r][c]);
        }
    }
    #pragma unroll
    for (int r = 0; r < 4; r++) {
        float s = 0.f;
        #pragma unroll
        for (int c = 0; c < C_; c++) {
            double v = (double)acc[r][c];
            #pragma unroll
            for (int off = 16; off; off >>= 1)
                v += __shfl_down_sync(0xffffffffu, v, off);
            if (lane == 0) {
                float cf = fmaxf((float)v, 0.f);
                cas[(size_t)(m0 + r) * C_ + c] = cf;
                s = __fadd_rn(s, cf);
            }
        }
        if (lane == 0) act[m0 + r] = s;
    }
}

// ============================================================
__device__ __forceinline__ void bitonic_sort_desc(float* val, int* idx, int tid) {
    for (int k = 2; k <= 1024; k <<= 1) {
        for (int j = k >> 1; j > 0; j >>= 1) {
            int p = tid ^ j;
            if (p > tid) {
                float v1 = val[tid], v2 = val[p];
                int i1 = idx[tid], i2 = idx[p];
                bool dirFwd = ((tid & k) == 0);
                bool p_before = (v2 > v1) || (v2 == v1 && i2 < i1);
                if (p_before == dirFwd) {
                    val[tid] = v2; val[p] = v1;
                    idx[tid] = i2; idx[p] = i1;
                }
            }
            __syncthreads();
        }
    }
}

__global__ __launch_bounds__(1024) void batch_topk(const float* __restrict__ act) {
    __shared__ float s_act[T_];
    __shared__ float s_bin[T_];
    __shared__ float s_val[1024];
    __shared__ int   s_idx[1024];
    __shared__ float s_med, s_max;

    const int b = blockIdx.x, tid = threadIdx.x;
    const float NEG = -CUDART_INF_F;

    if (tid < T_) s_act[tid] = act[b * T_ + tid];
    __syncthreads();

    s_val[tid] = (tid < T_) ? s_act[tid] : NEG;
    __syncthreads();
    for (int off = 512; off; off >>= 1) {
        if (tid < off) s_val[tid] = fmaxf(s_val[tid], s_val[tid + off]);
        __syncthreads();
    }
    if (tid == 0) s_max = s_val[0];
    __syncthreads();

    s_val[tid] = (tid < T_) ? s_act[tid] : NEG;
    s_idx[tid] = (tid < T_) ? tid : (1 << 20);
    __syncthreads();
    bitonic_sort_desc(s_val, s_idx, tid);
    if (tid < K_EASY) g_idx[b * K_EASY + tid] = s_idx[tid];
    if (tid == 0) s_med = 0.5f * (s_val[374] + s_val[375]);
    __syncthreads();

    s_val[tid] = (tid < T_) ? __fsub_rn(s_max, s_act[tid]) : NEG;
    s_idx[tid] = (tid < T_) ? tid : (1 << 20);
    __syncthreads();
    bitonic_sort_desc(s_val, s_idx, tid);
    if (tid < K_EASY) g_idx[B_ * K_EASY + b * K_EASY + tid] = s_idx[tid];
    __syncthreads();

    if (tid < T_) s_bin[tid] = (s_act[tid] > s_med) ? 1.0f : 0.0f;
    __syncthreads();

    float sc = NEG;
    if (tid < T_) {
        float e3 = 1.f, e6 = 1.f;
        #pragma unroll
        for (int u = -1; u <= 1; u++) {
            int q = tid + u;
            e3 = fminf(e3, (q >= 0 && q < T_) ? s_bin[q] : 0.f);
        }
        #pragma unroll
        for (int u = -3; u <= 2; u++) {
            int q = tid + u;
            e6 = fminf(e6, (q >= 0 && q < T_) ? s_bin[q] : 0.f);
        }
        sc = s_act[tid] * (e3 - e6);
    }
    s_val[tid] = (tid < T_) ? sc : NEG;
    s_idx[tid] = (tid < T_) ? tid : (1 << 20);
    __syncthreads();
    bitonic_sort_desc(s_val, s_idx, tid);
    if (tid < K_HARD) g_idx[2 * B_ * K_EASY + b * K_HARD + tid] = s_idx[tid];
    __syncthreads();

    sc = NEG;
    if (tid < T_) {
        float d3 = 0.f, d6 = 0.f;
        #pragma unroll
        for (int u = -1; u <= 1; u++) {
            int q = tid + u;
            d3 = fmaxf(d3, (q >= 0 && q < T_) ? s_bin[q] : 0.f);
        }
        #pragma unroll
        for (int u = -2; u <= 3; u++) {
            int q = tid + u;
            d6 = fmaxf(d6, (q >= 0 && q < T_) ? s_bin[q] : 0.f);
        }
        sc = s_act[tid] * (d6 - d3);
    }
    s_val[tid] = (tid < T_) ? sc : NEG;
    s_idx[tid] = (tid < T_) ? tid : (1 << 20);
    __syncthreads();
    bitonic_sort_desc(s_val, s_idx, tid);
    if (tid < K_HARD)
        g_idx[2 * B_ * K_EASY + B_ * K_HARD + b * K_HARD + tid] = s_idx[tid];
}

__global__ __launch_bounds__(1024) void video_topk(const float* __restrict__ cas) {
    __shared__ float s_val[1024];
    __shared__ int   s_idx[1024];
    __shared__ float red[32];
    int bc = blockIdx.x;
    int b = bc / C_, c = bc - b * C_;
    int tid = threadIdx.x;
    s_val[tid] = (tid < T_) ? cas[(size_t)(b * T_ + tid) * C_ + c] : -CUDART_INF_F;
    s_idx[tid] = tid;
    __syncthreads();
    bitonic_sort_desc(s_val, s_idx, tid);
    float v = (tid < K_EASY) ? s_val[tid] : 0.f;
    #pragma unroll
    for (int off = 16; off; off >>= 1) v += __shfl_down_sync(0xffffffffu, v, off);
    if ((tid & 31) == 0) red[tid >> 5] = v;
    __syncthreads();
    if (tid < 32) {
        float t = red[tid];
        #pragma unroll
        for (int off = 16; off; off >>= 1) t += __shfl_down_sync(0xffffffffu, t, off);
        if (tid == 0) g_means[b * C_ + c] = t / (float)K_EASY;
    }
}

__global__ void softmax_k(float* __restrict__ out) {
    int b = blockIdx.x;
    int lane = threadIdx.x;
    float v = (lane < C_) ? g_means[b * C_ + lane] : -CUDART_INF_F;
    float mx = v;
    #pragma unroll
    for (int off = 16; off; off >>= 1) mx = fmaxf(mx, __shfl_xor_sync(0xffffffffu, mx, off));
    float e = (lane < C_) ? expf(v - mx) : 0.f;
    float s = e;
    #pragma unroll
    for (int off = 16; off; off >>= 1) s += __shfl_xor_sync(0xffffffffu, s, off);
    if (lane < C_) out[b * C_ + lane] = e / s;
}

__global__ __launch_bounds__(256) void gather_k(float* __restrict__ out) {
    int r = blockIdx.x;
    int b, t;
    size_t dst;
    if (r < B_ * K_EASY) {
        b = r / K_EASY; t = g_idx[r];
        dst = OFF_EA + (size_t)r * D_;
    } else if (r < 2 * B_ * K_EASY) {
        int rr = r - B_ * K_EASY;
        b = rr / K_EASY; t = g_idx[r];
        dst = OFF_EB + (size_t)rr * D_;
    } else if (r < 2 * B_ * K_EASY + B_ * K_HARD) {
        int rr = r - 2 * B_ * K_EASY;
        b = rr / K_HARD; t = g_idx[r];
        dst = OFF_HA + (size_t)rr * D_;
    } else {
        int rr = r - 2 * B_ * K_EASY - B_ * K_HARD;
        b = rr / K_HARD; t = g_idx[r];
        dst = OFF_HB + (size_t)rr * D_;
    }
    const float4* src = (const float4*)(g_h + ((size_t)(b * T_ + t) << 11));
    float4* d = (float4*)(out + dst);
    for (int i = threadIdx.x; i < D_ / 4; i += blockDim.x) d[i] = src[i];
}

// ============================================================
extern "C" void kernel_launch(void* const* d_in, const int* in_sizes, int n_in,
                              void* d_out, int out_size) {
    const float* x  = (const float*)d_in[0];
    const float* w1 = (const float*)d_in[1];
    const float* b1 = (const float*)d_in[2];
    const float* w2 = (const float*)d_in[3];
    float* out = (float*)d_out;

    cudaFuncSetAttribute(conv1_f16, cudaFuncAttributeMaxDynamicSharedMemorySize, DSMEM);

    pad_split_x<<<(B_ * 752 * (D_ / 4) + 255) / 256, 256>>>(x);
    {
        size_t tot = (size_t)D_ * K_DIM;
        split_w<<<(unsigned)((tot + 255) / 256), 256>>>(w1);
    }
    repack_w2_k<<<(D_ * C_ + 255) / 256, 256>>>(w2);
    {
        dim3 g(D_ / 64, (M_TOTAL + 63) / 64);   // (32, 188)
        conv1_f16<<<g, 128, DSMEM>>>(b1);
    }
    cas_kernel<<<(M_TOTAL / 4 + 7) / 8, 256>>>(out + OFF_CAS, out + OFF_ACT);
    batch_topk<<<B_, 1024>>>(out + OFF_ACT);
    video_topk<<<B_ * C_, 1024>>>(out + OFF_CAS);
    softmax_k<<<B_, 32>>>(out + OFF_VS);
    gather_k<<<2 * B_ * K_EASY + 2 * B_ * K_HARD, 256>>>(out);
}